// round 15
// baseline (speedup 1.0000x reference)
#include <cuda_runtime.h>
#include <cuda_fp16.h>
#include <stdint.h>

#define LUT_N 35937                   // 33^3 entries per channel
#define CH_STRIDE 35937
#define HW (1080 * 1920)
#define HW2 (HW / 2)                  // float2 groups per plane
#define NBATCH 4
#define NV2 (NBATCH * HW2)            // 4,147,200 float2 groups
#define NBLOCKS 152                   // one persistent CTA per SM
#define NTHREADS 1024
#define STRIDE (NBLOCKS * NTHREADS)   // 155,648 < HW2 -> incremental indexing valid
// SMEM layout: c01 table (half2 {c0,c1}, 4B/entry) then c2 table (half, 2B/entry)
#define C01_BYTES (LUT_N * 4)                       // 143,748
#define SMEM_BYTES (LUT_N * 4 + LUT_N * 2)          // 215,622 B (< 227 KB)
#define SCRATCH_BYTES ((SMEM_BYTES + 15) & ~15)     // 215,632 (16B-padded)

// Staged fp16 tables, exact SMEM image (built once by pack kernel).
__device__ __align__(16) unsigned char g_staged[SCRATCH_BYTES];

__global__ void pack_lut_kernel(const float* __restrict__ LUT) {
    int i = blockIdx.x * blockDim.x + threadIdx.x;
    if (i >= LUT_N) return;
    __half2 h = __floats2half2_rn(LUT[i], LUT[i + CH_STRIDE]);
    *reinterpret_cast<unsigned int*>(g_staged + 4 * (size_t)i) =
        *reinterpret_cast<unsigned int*>(&h);
    __half h2 = __float2half_rn(LUT[i + 2 * CH_STRIDE]);
    *reinterpret_cast<unsigned short*>(g_staged + C01_BYTES + 2 * (size_t)i) =
        *reinterpret_cast<unsigned short*>(&h2);
}

__device__ __forceinline__ float2 h2f(unsigned int u) {
    __half2 h = *reinterpret_cast<__half2*>(&u);
    return __half22float2(h);
}
__device__ __forceinline__ float2 lerp2(float2 a, float2 b, float f) {
    return make_float2(fmaf(f, b.x - a.x, a.x), fmaf(f, b.y - a.y, a.y));
}
__device__ __forceinline__ uint32_t smem_u32(const void* p) {
    uint32_t a;
    asm("{ .reg .u64 t; cvta.to.shared.u64 t, %1; cvt.u32.u64 %0, t; }"
        : "=r"(a) : "l"(p));
    return a;
}

__global__ void __launch_bounds__(NTHREADS, 1)
lut_apply_smem(const float* __restrict__ x, float* __restrict__ out) {
    extern __shared__ unsigned char smem[];
    unsigned int*   __restrict__ c01 = reinterpret_cast<unsigned int*>(smem);
    unsigned short* __restrict__ c2u = reinterpret_cast<unsigned short*>(smem + C01_BYTES);

    const float2* __restrict__ xf = reinterpret_cast<const float2*>(x);
    float2*       __restrict__ of = reinterpret_cast<float2*>(out);

    int v = blockIdx.x * NTHREADS + threadIdx.x;   // logical float2-group index

    // Incremental indexing state: j = within-plane index, o = element offset of
    // the r-plane entry (= b*3*HW2 + j). One division total, at the prologue.
    int b0 = v / HW2;
    int j  = v - b0 * HW2;
    int o  = b0 * (3 * HW2) + j;

    // ── Streaming prologue FIRST: overlaps DRAM latency with the SMEM fill ──
    float2 r2 = __ldcs(xf + o);
    float2 g2 = __ldcs(xf + o + HW2);
    float2 b2 = __ldcs(xf + o + 2 * HW2);

    // ── SMEM fill via cp.async: no register round-trip, fully pipelined ──
    {
        const unsigned char* src = g_staged;
        uint32_t dst = smem_u32(smem);
        for (int ofs = threadIdx.x * 16; ofs < SCRATCH_BYTES; ofs += NTHREADS * 16) {
            asm volatile("cp.async.cg.shared.global [%0], [%1], 16;"
                         :: "r"(dst + ofs), "l"(src + ofs));
        }
        asm volatile("cp.async.commit_group;");
        asm volatile("cp.async.wait_group 0;");
    }
    __syncthreads();

    while (true) {
        // ── Incremental next-index computation (no division) ──
        int vn = v + STRIDE;
        int jn = j + STRIDE;
        int on = o + STRIDE;
        if (jn >= HW2) { jn -= HW2; on += 2 * HW2; }   // ISETP + SEL, branchless
        bool more = vn < NV2;
        int  po   = more ? on : o;                     // clamped prefetch offset

        // ── Branchless clamped prefetch of next streaming triple ──
        float2 nr2 = __ldcs(xf + po);
        float2 ng2 = __ldcs(xf + po + HW2);
        float2 nb2 = __ldcs(xf + po + 2 * HW2);

        // ── Indices/fracs for both pixels ──
        float rs[2] = { r2.x, r2.y };
        float gs[2] = { g2.x, g2.y };
        float bs[2] = { b2.x, b2.y };
        int   q[2];
        float fr[2], fg[2], fb[2];
#pragma unroll
        for (int i = 0; i < 2; i++) {
            float sr = __saturatef(rs[i]) * 32.0f;
            float sg = __saturatef(gs[i]) * 32.0f;
            float sb = __saturatef(bs[i]) * 32.0f;
            int ri = min((int)sr, 31);
            int gi = min((int)sg, 31);
            int bi = min((int)sb, 31);
            fr[i] = sr - (float)ri;
            fg[i] = sg - (float)gi;
            fb[i] = sb - (float)bi;
            q[i]  = (bi * 33 + gi) * 33 + ri;
        }

        // ── Issue ALL 32 gathers for both pixels before any math ──
        unsigned int   a[2][8];
        unsigned short z[2][8];
#pragma unroll
        for (int t = 0; t < 2; t++) {
            int qq = q[t];
            a[t][0] = c01[qq];          a[t][1] = c01[qq + 1];
            a[t][2] = c01[qq + 33];     a[t][3] = c01[qq + 34];
            a[t][4] = c01[qq + 1089];   a[t][5] = c01[qq + 1090];
            a[t][6] = c01[qq + 1122];   a[t][7] = c01[qq + 1123];
            z[t][0] = c2u[qq];          z[t][1] = c2u[qq + 1];
            z[t][2] = c2u[qq + 33];     z[t][3] = c2u[qq + 34];
            z[t][4] = c2u[qq + 1089];   z[t][5] = c2u[qq + 1090];
            z[t][6] = c2u[qq + 1122];   z[t][7] = c2u[qq + 1123];
        }

        float o0[2], o1[2], o2[2];
#pragma unroll
        for (int t = 0; t < 2; t++) {
            float2 e00 = lerp2(h2f(a[t][0]), h2f(a[t][1]), fr[t]);
            float2 e01 = lerp2(h2f(a[t][2]), h2f(a[t][3]), fr[t]);
            float2 e10 = lerp2(h2f(a[t][4]), h2f(a[t][5]), fr[t]);
            float2 e11 = lerp2(h2f(a[t][6]), h2f(a[t][7]), fr[t]);
            float2 eg0 = lerp2(e00, e01, fg[t]);
            float2 eg1 = lerp2(e10, e11, fg[t]);
            float2 ec  = lerp2(eg0, eg1, fb[t]);

            float z0 = __half2float(__ushort_as_half(z[t][0]));
            float z1 = __half2float(__ushort_as_half(z[t][1]));
            float z2 = __half2float(__ushort_as_half(z[t][2]));
            float z3 = __half2float(__ushort_as_half(z[t][3]));
            float z4 = __half2float(__ushort_as_half(z[t][4]));
            float z5 = __half2float(__ushort_as_half(z[t][5]));
            float z6 = __half2float(__ushort_as_half(z[t][6]));
            float z7 = __half2float(__ushort_as_half(z[t][7]));
            float s00 = fmaf(fr[t], z1 - z0, z0);
            float s01 = fmaf(fr[t], z3 - z2, z2);
            float s10 = fmaf(fr[t], z5 - z4, z4);
            float s11 = fmaf(fr[t], z7 - z6, z6);
            float sg0 = fmaf(fg[t], s01 - s00, s00);
            float sg1 = fmaf(fg[t], s11 - s10, s10);
            float sc  = fmaf(fb[t], sg1 - sg0, sg0);

            o0[t] = ec.x; o1[t] = ec.y; o2[t] = sc;
        }

        __stcs(of + o,           make_float2(o0[0], o0[1]));
        __stcs(of + o + HW2,     make_float2(o1[0], o1[1]));
        __stcs(of + o + 2 * HW2, make_float2(o2[0], o2[1]));

        if (!more) break;
        v = vn; j = jn; o = on;
        r2 = nr2; g2 = ng2; b2 = nb2;
    }
}

extern "C" void kernel_launch(void* const* d_in, const int* in_sizes, int n_in,
                              void* d_out, int out_size) {
    const float* x   = (const float*)d_in[0];   // (4,3,1080,1920) fp32
    const float* LUT = (const float*)d_in[1];   // (3,33,33,33) fp32
    float* out = (float*)d_out;

    static bool smem_ok = []() {
        cudaFuncSetAttribute(lut_apply_smem,
                             cudaFuncAttributeMaxDynamicSharedMemorySize,
                             SMEM_BYTES);
        return true;
    }();
    (void)smem_ok;

    pack_lut_kernel<<<(LUT_N + 511) / 512, 512>>>(LUT);
    lut_apply_smem<<<NBLOCKS, NTHREADS, SMEM_BYTES>>>(x, out);
}

// round 16
// speedup vs baseline: 1.0417x; 1.0417x over previous
#include <cuda_runtime.h>
#include <cuda_fp16.h>
#include <stdint.h>

#define LUT_N 35937                   // 33^3 entries per channel
#define CH_STRIDE 35937
#define HW (1080 * 1920)
#define HW2 (HW / 2)                  // float2 groups per plane
#define NBATCH 4
#define NV2 (NBATCH * HW2)            // 4,147,200 float2 groups
#define NBLOCKS 152                   // one persistent CTA per SM
#define NTHREADS 1024
#define STRIDE (NBLOCKS * NTHREADS)   // 155,648 < HW2 -> incremental indexing valid
// SMEM layout: c01 table (half2 {c0,c1}, 4B/entry) then zp pair table
// zp[(b*33+g)*17 + k] = half2 { c2[...,2k], c2[...,2k+1] }  (k in [0,16], hi of k=16 = pad)
#define ZP_ROW 17
#define ZP_N (33 * 33 * ZP_ROW)                     // 18,513 pair entries
#define C01_BYTES (LUT_N * 4)                       // 143,748
#define ZP_BYTES (ZP_N * 4)                         // 74,052
#define SMEM_BYTES (C01_BYTES + ZP_BYTES)           // 217,800 B (< 227 KB)
#define SCRATCH_BYTES ((SMEM_BYTES + 15) & ~15)     // 217,808 (16B-padded)

// Staged fp16 tables, exact SMEM image (built once by pack kernel).
__device__ __align__(16) unsigned char g_staged[SCRATCH_BYTES];

__global__ void pack_lut_kernel(const float* __restrict__ LUT) {
    int i = blockIdx.x * blockDim.x + threadIdx.x;
    if (i < LUT_N) {
        __half2 h = __floats2half2_rn(LUT[i], LUT[i + CH_STRIDE]);
        *reinterpret_cast<unsigned int*>(g_staged + 4 * (size_t)i) =
            *reinterpret_cast<unsigned int*>(&h);
    }
    if (i < ZP_N) {
        int k = i % ZP_ROW;           // r-pair index: covers r = 2k, 2k+1
        int t = i / ZP_ROW;           // b*33 + g
        int base = t * 33 + 2 * k;    // source index in c2 plane
        float v0 = LUT[base + 2 * CH_STRIDE];
        float v1 = (k < 16) ? LUT[base + 1 + 2 * CH_STRIDE] : 0.0f;  // k=16: pad hi
        __half2 h = __floats2half2_rn(v0, v1);
        *reinterpret_cast<unsigned int*>(g_staged + C01_BYTES + 4 * (size_t)i) =
            *reinterpret_cast<unsigned int*>(&h);
    }
}

__device__ __forceinline__ float2 h2f(unsigned int u) {
    __half2 h = *reinterpret_cast<__half2*>(&u);
    return __half22float2(h);
}
__device__ __forceinline__ float2 lerp2(float2 a, float2 b, float f) {
    return make_float2(fmaf(f, b.x - a.x, a.x), fmaf(f, b.y - a.y, a.y));
}
__device__ __forceinline__ uint32_t smem_u32(const void* p) {
    uint32_t a;
    asm("{ .reg .u64 t; cvta.to.shared.u64 t, %1; cvt.u32.u64 %0, t; }"
        : "=r"(a) : "l"(p));
    return a;
}

__global__ void __launch_bounds__(NTHREADS, 1)
lut_apply_smem(const float* __restrict__ x, float* __restrict__ out) {
    extern __shared__ unsigned char smem[];
    unsigned int* __restrict__ c01 = reinterpret_cast<unsigned int*>(smem);
    unsigned int* __restrict__ zpt = reinterpret_cast<unsigned int*>(smem + C01_BYTES);

    const float2* __restrict__ xf = reinterpret_cast<const float2*>(x);
    float2*       __restrict__ of = reinterpret_cast<float2*>(out);

    int v = blockIdx.x * NTHREADS + threadIdx.x;   // logical float2-group index

    int b0 = v / HW2;
    int j  = v - b0 * HW2;
    int o  = b0 * (3 * HW2) + j;

    // ── Streaming prologue FIRST: overlaps DRAM latency with the SMEM fill ──
    float2 r2 = __ldcs(xf + o);
    float2 g2 = __ldcs(xf + o + HW2);
    float2 b2 = __ldcs(xf + o + 2 * HW2);

    // ── SMEM fill via cp.async: no register round-trip, fully pipelined ──
    {
        const unsigned char* src = g_staged;
        uint32_t dst = smem_u32(smem);
        for (int ofs = threadIdx.x * 16; ofs < SCRATCH_BYTES; ofs += NTHREADS * 16) {
            asm volatile("cp.async.cg.shared.global [%0], [%1], 16;"
                         :: "r"(dst + ofs), "l"(src + ofs));
        }
        asm volatile("cp.async.commit_group;");
        asm volatile("cp.async.wait_group 0;");
    }
    __syncthreads();

    while (true) {
        // ── Incremental next-index computation (no division) ──
        int vn = v + STRIDE;
        int jn = j + STRIDE;
        int on = o + STRIDE;
        if (jn >= HW2) { jn -= HW2; on += 2 * HW2; }
        bool more = vn < NV2;
        int  po   = more ? on : o;

        // ── Branchless clamped prefetch of next streaming triple ──
        float2 nr2 = __ldcs(xf + po);
        float2 ng2 = __ldcs(xf + po + HW2);
        float2 nb2 = __ldcs(xf + po + 2 * HW2);

        // ── Indices/fracs for both pixels ──
        float rs[2] = { r2.x, r2.y };
        float gs[2] = { g2.x, g2.y };
        float bs[2] = { b2.x, b2.y };
        int   q[2], qz[2];
        bool  ro[2];
        float fr[2], fg[2], fb[2];
#pragma unroll
        for (int i = 0; i < 2; i++) {
            float sr = __saturatef(rs[i]) * 32.0f;
            float sg = __saturatef(gs[i]) * 32.0f;
            float sb = __saturatef(bs[i]) * 32.0f;
            int ri = min((int)sr, 31);
            int gi = min((int)sg, 31);
            int bi = min((int)sb, 31);
            fr[i] = sr - (float)ri;
            fg[i] = sg - (float)gi;
            fb[i] = sb - (float)bi;
            int cell = bi * 33 + gi;
            q[i]  = cell * 33 + ri;
            qz[i] = cell * ZP_ROW + (ri >> 1);
            ro[i] = (ri & 1) != 0;
        }

        // ── Gathers for both pixels: c01 (8 LDS.32/px) + zp pairs
        //    (4 LDS.32 + 4 predicated LDS.32 per px, ~half lanes active) ──
        unsigned int a[2][8];
        unsigned int zp0[2][4], zp1[2][4];
        const int ZOFF[4] = { 0, ZP_ROW, 33 * ZP_ROW, 34 * ZP_ROW };
#pragma unroll
        for (int t = 0; t < 2; t++) {
            int qq = q[t];
            a[t][0] = c01[qq];          a[t][1] = c01[qq + 1];
            a[t][2] = c01[qq + 33];     a[t][3] = c01[qq + 34];
            a[t][4] = c01[qq + 1089];   a[t][5] = c01[qq + 1090];
            a[t][6] = c01[qq + 1122];   a[t][7] = c01[qq + 1123];
#pragma unroll
            for (int c = 0; c < 4; c++) {
                int zi = qz[t] + ZOFF[c];
                zp0[t][c] = zpt[zi];
                unsigned int p1 = zp0[t][c];
                if (ro[t]) p1 = zpt[zi + 1];   // predicated: ~16 active lanes
                zp1[t][c] = p1;
            }
        }

        float o0[2], o1[2], o2[2];
#pragma unroll
        for (int t = 0; t < 2; t++) {
            float2 e00 = lerp2(h2f(a[t][0]), h2f(a[t][1]), fr[t]);
            float2 e01 = lerp2(h2f(a[t][2]), h2f(a[t][3]), fr[t]);
            float2 e10 = lerp2(h2f(a[t][4]), h2f(a[t][5]), fr[t]);
            float2 e11 = lerp2(h2f(a[t][6]), h2f(a[t][7]), fr[t]);
            float2 eg0 = lerp2(e00, e01, fg[t]);
            float2 eg1 = lerp2(e10, e11, fg[t]);
            float2 ec  = lerp2(eg0, eg1, fb[t]);

            // c2 channel from pair loads: even r -> both in pair k;
            // odd r -> z[r]=hi(pair k), z[r+1]=lo(pair k+1)
            float s[4];
#pragma unroll
            for (int c = 0; c < 4; c++) {
                float2 f0 = h2f(zp0[t][c]);
                float2 f1 = h2f(zp1[t][c]);
                float zr  = ro[t] ? f0.y : f0.x;
                float zr1 = ro[t] ? f1.x : f0.y;
                s[c] = fmaf(fr[t], zr1 - zr, zr);
            }
            float sg0 = fmaf(fg[t], s[1] - s[0], s[0]);
            float sg1 = fmaf(fg[t], s[3] - s[2], s[2]);
            float sc  = fmaf(fb[t], sg1 - sg0, sg0);

            o0[t] = ec.x; o1[t] = ec.y; o2[t] = sc;
        }

        __stcs(of + o,           make_float2(o0[0], o0[1]));
        __stcs(of + o + HW2,     make_float2(o1[0], o1[1]));
        __stcs(of + o + 2 * HW2, make_float2(o2[0], o2[1]));

        if (!more) break;
        v = vn; j = jn; o = on;
        r2 = nr2; g2 = ng2; b2 = nb2;
    }
}

extern "C" void kernel_launch(void* const* d_in, const int* in_sizes, int n_in,
                              void* d_out, int out_size) {
    const float* x   = (const float*)d_in[0];   // (4,3,1080,1920) fp32
    const float* LUT = (const float*)d_in[1];   // (3,33,33,33) fp32
    float* out = (float*)d_out;

    static bool smem_ok = []() {
        cudaFuncSetAttribute(lut_apply_smem,
                             cudaFuncAttributeMaxDynamicSharedMemorySize,
                             SCRATCH_BYTES);
        return true;
    }();
    (void)smem_ok;

    pack_lut_kernel<<<(LUT_N + 511) / 512, 512>>>(LUT);
    lut_apply_smem<<<NBLOCKS, NTHREADS, SCRATCH_BYTES>>>(x, out);
}

// round 17
// speedup vs baseline: 1.0678x; 1.0251x over previous
#include <cuda_runtime.h>
#include <cuda_fp16.h>
#include <stdint.h>

#define LUT_N 35937                   // 33^3 entries per channel
#define CH_STRIDE 35937
#define HW (1080 * 1920)
#define HW2 (HW / 2)                  // float2 groups per plane
#define NBATCH 4
#define NV2 (NBATCH * HW2)            // 4,147,200 float2 groups
#define NBLOCKS 152                   // one persistent CTA per SM
#define NTHREADS 1024
#define STRIDE (NBLOCKS * NTHREADS)   // 155,648 < HW2 -> incremental indexing valid
// SMEM layout: c01 table (half2 {c0,c1}, 4B/entry) then zp pair table
// zp[(b*33+g)*17 + k] = half2 { c2[...,2k], c2[...,2k+1] }  (k in [0,16], hi of k=16 = pad)
#define ZP_ROW 17
#define ZP_N (33 * 33 * ZP_ROW)                     // 18,513 pair entries
#define C01_BYTES (LUT_N * 4)                       // 143,748
#define ZP_BYTES (ZP_N * 4)                         // 74,052
#define SMEM_BYTES (C01_BYTES + ZP_BYTES)           // 217,800 B (< 227 KB)
#define SCRATCH_BYTES ((SMEM_BYTES + 15) & ~15)     // 217,808 (16B-padded)

// Staged fp16 tables, exact SMEM image (built once by pack kernel).
__device__ __align__(16) unsigned char g_staged[SCRATCH_BYTES];

__global__ void pack_lut_kernel(const float* __restrict__ LUT) {
    int i = blockIdx.x * blockDim.x + threadIdx.x;
    if (i < LUT_N) {
        __half2 h = __floats2half2_rn(LUT[i], LUT[i + CH_STRIDE]);
        *reinterpret_cast<unsigned int*>(g_staged + 4 * (size_t)i) =
            *reinterpret_cast<unsigned int*>(&h);
    }
    if (i < ZP_N) {
        int k = i % ZP_ROW;           // r-pair index: covers r = 2k, 2k+1
        int t = i / ZP_ROW;           // b*33 + g
        int base = t * 33 + 2 * k;    // source index in c2 plane
        float v0 = LUT[base + 2 * CH_STRIDE];
        float v1 = (k < 16) ? LUT[base + 1 + 2 * CH_STRIDE] : 0.0f;  // k=16: pad hi
        __half2 h = __floats2half2_rn(v0, v1);
        *reinterpret_cast<unsigned int*>(g_staged + C01_BYTES + 4 * (size_t)i) =
            *reinterpret_cast<unsigned int*>(&h);
    }
}

__device__ __forceinline__ float2 h2f(unsigned int u) {
    __half2 h = *reinterpret_cast<__half2*>(&u);
    return __half22float2(h);
}
__device__ __forceinline__ float2 lerp2(float2 a, float2 b, float f) {
    return make_float2(fmaf(f, b.x - a.x, a.x), fmaf(f, b.y - a.y, a.y));
}
__device__ __forceinline__ uint32_t smem_u32(const void* p) {
    uint32_t a;
    asm("{ .reg .u64 t; cvta.to.shared.u64 t, %1; cvt.u32.u64 %0, t; }"
        : "=r"(a) : "l"(p));
    return a;
}

__global__ void __launch_bounds__(NTHREADS, 1)
lut_apply_smem(const float* __restrict__ x, float* __restrict__ out) {
    extern __shared__ unsigned char smem[];
    unsigned int* __restrict__ c01 = reinterpret_cast<unsigned int*>(smem);
    unsigned int* __restrict__ zpt = reinterpret_cast<unsigned int*>(smem + C01_BYTES);

    const float2* __restrict__ xf = reinterpret_cast<const float2*>(x);
    float2*       __restrict__ of = reinterpret_cast<float2*>(out);

    int v = blockIdx.x * NTHREADS + threadIdx.x;   // logical float2-group index

    int b0 = v / HW2;
    int j  = v - b0 * HW2;
    int o  = b0 * (3 * HW2) + j;

    // ── Streaming prologue FIRST: overlaps DRAM latency with the SMEM fill ──
    float2 r2 = __ldcs(xf + o);
    float2 g2 = __ldcs(xf + o + HW2);
    float2 b2 = __ldcs(xf + o + 2 * HW2);

    // ── SMEM fill via cp.async: no register round-trip, fully pipelined ──
    {
        const unsigned char* src = g_staged;
        uint32_t dst = smem_u32(smem);
        for (int ofs = threadIdx.x * 16; ofs < SCRATCH_BYTES; ofs += NTHREADS * 16) {
            asm volatile("cp.async.cg.shared.global [%0], [%1], 16;"
                         :: "r"(dst + ofs), "l"(src + ofs));
        }
        asm volatile("cp.async.commit_group;");
        asm volatile("cp.async.wait_group 0;");
    }
    __syncthreads();

    while (true) {
        // ── Incremental next-index computation (no division) ──
        int vn = v + STRIDE;
        int jn = j + STRIDE;
        int on = o + STRIDE;
        if (jn >= HW2) { jn -= HW2; on += 2 * HW2; }
        bool more = vn < NV2;
        int  po   = more ? on : o;

        // ── Branchless clamped prefetch of next streaming triple ──
        float2 nr2 = __ldcs(xf + po);
        float2 ng2 = __ldcs(xf + po + HW2);
        float2 nb2 = __ldcs(xf + po + 2 * HW2);

        // ── Indices/fracs for both pixels ──
        float rs[2] = { r2.x, r2.y };
        float gs[2] = { g2.x, g2.y };
        float bs[2] = { b2.x, b2.y };
        int   q[2], qz[2];
        unsigned int sh[2];            // 0 for even r, 16 for odd r
        float fr[2], fg[2], fb[2];
#pragma unroll
        for (int i = 0; i < 2; i++) {
            float sr = __saturatef(rs[i]) * 32.0f;
            float sg = __saturatef(gs[i]) * 32.0f;
            float sb = __saturatef(bs[i]) * 32.0f;
            int ri = min((int)sr, 31);
            int gi = min((int)sg, 31);
            int bi = min((int)sb, 31);
            fr[i] = sr - (float)ri;
            fg[i] = sg - (float)gi;
            fb[i] = sb - (float)bi;
            int cell = bi * 33 + gi;
            q[i]  = cell * 33 + ri;
            qz[i] = cell * ZP_ROW + (ri >> 1);
            sh[i] = (unsigned int)(ri & 1) << 4;
        }

        // ── Gathers for both pixels: c01 (8 LDS.32/px) + zp pairs
        //    (4 LDS.32 + 4 predicated LDS.32 per px, ~half lanes active);
        //    funnel-shift fuses even/odd decode into one SHF per corner. ──
        unsigned int a[2][8];
        unsigned int zsel[2][4];
        const int ZOFF[4] = { 0, ZP_ROW, 33 * ZP_ROW, 34 * ZP_ROW };
#pragma unroll
        for (int t = 0; t < 2; t++) {
            int qq = q[t];
            a[t][0] = c01[qq];          a[t][1] = c01[qq + 1];
            a[t][2] = c01[qq + 33];     a[t][3] = c01[qq + 34];
            a[t][4] = c01[qq + 1089];   a[t][5] = c01[qq + 1090];
            a[t][6] = c01[qq + 1122];   a[t][7] = c01[qq + 1123];
            bool odd = sh[t] != 0;
#pragma unroll
            for (int c = 0; c < 4; c++) {
                int zi = qz[t] + ZOFF[c];
                unsigned int p0 = zpt[zi];
                unsigned int p1 = p0;
                if (odd) p1 = zpt[zi + 1];          // predicated: ~16 active lanes
                // {z[r], z[r+1]} = ((p1:p0) >> sh) low 32 bits
                zsel[t][c] = __funnelshift_r(p0, p1, sh[t]);
            }
        }

        float o0[2], o1[2], o2[2];
#pragma unroll
        for (int t = 0; t < 2; t++) {
            float2 e00 = lerp2(h2f(a[t][0]), h2f(a[t][1]), fr[t]);
            float2 e01 = lerp2(h2f(a[t][2]), h2f(a[t][3]), fr[t]);
            float2 e10 = lerp2(h2f(a[t][4]), h2f(a[t][5]), fr[t]);
            float2 e11 = lerp2(h2f(a[t][6]), h2f(a[t][7]), fr[t]);
            float2 eg0 = lerp2(e00, e01, fg[t]);
            float2 eg1 = lerp2(e10, e11, fg[t]);
            float2 ec  = lerp2(eg0, eg1, fb[t]);

            // c2 channel: each zsel holds {z[r], z[r+1]} -> one fma per corner
            float s[4];
#pragma unroll
            for (int c = 0; c < 4; c++) {
                float2 zz = h2f(zsel[t][c]);
                s[c] = fmaf(fr[t], zz.y - zz.x, zz.x);
            }
            float sg0 = fmaf(fg[t], s[1] - s[0], s[0]);
            float sg1 = fmaf(fg[t], s[3] - s[2], s[2]);
            float sc  = fmaf(fb[t], sg1 - sg0, sg0);

            o0[t] = ec.x; o1[t] = ec.y; o2[t] = sc;
        }

        __stcs(of + o,           make_float2(o0[0], o0[1]));
        __stcs(of + o + HW2,     make_float2(o1[0], o1[1]));
        __stcs(of + o + 2 * HW2, make_float2(o2[0], o2[1]));

        if (!more) break;
        v = vn; j = jn; o = on;
        r2 = nr2; g2 = ng2; b2 = nb2;
    }
}

extern "C" void kernel_launch(void* const* d_in, const int* in_sizes, int n_in,
                              void* d_out, int out_size) {
    const float* x   = (const float*)d_in[0];   // (4,3,1080,1920) fp32
    const float* LUT = (const float*)d_in[1];   // (3,33,33,33) fp32
    float* out = (float*)d_out;

    static bool smem_ok = []() {
        cudaFuncSetAttribute(lut_apply_smem,
                             cudaFuncAttributeMaxDynamicSharedMemorySize,
                             SCRATCH_BYTES);
        return true;
    }();
    (void)smem_ok;

    pack_lut_kernel<<<(LUT_N + 511) / 512, 512>>>(LUT);
    lut_apply_smem<<<NBLOCKS, NTHREADS, SCRATCH_BYTES>>>(x, out);
}